// round 4
// baseline (speedup 1.0000x reference)
#include <cuda_runtime.h>
#include <math.h>
#include <stdint.h>

#define B_   2
#define S_   1024
#define E_   2048
#define NH_  16
#define DH_  128
#define EPS_ 1e-6f
#define NEC  12          // e-chunks for gates GEMM split-K
#define ECH  512         // 6144 / 12

// ---------------- f32x2 helpers (Blackwell packed fp32) ----------------
#define FMA2(d, a, b)  asm("fma.rn.f32x2 %0, %1, %2, %0;" : "+l"(d) : "l"(a), "l"(b))
#define PACK2(d, x)    asm("mov.b64 %0, {%1, %1};" : "=l"(d) : "f"(x))

__device__ __forceinline__ void cpa16(uint32_t dst, const void* src) {
    asm volatile("cp.async.ca.shared.global [%0], [%1], 16;" :: "r"(dst), "l"(src));
}
__device__ __forceinline__ void cpa8(uint32_t dst, const void* src) {
    asm volatile("cp.async.ca.shared.global [%0], [%1], 8;" :: "r"(dst), "l"(src));
}
__device__ __forceinline__ void cpa_commit() { asm volatile("cp.async.commit_group;"); }

// -------- device scratch (no allocations allowed) --------
__device__ float g_part[2 * NEC * B_ * NH_ * S_];   // gate partial sums
__device__ float g_a [B_ * NH_ * S_];               // a[j] = ig[j] - cum[j]
__device__ float g_rm[B_ * NH_ * S_];               // prefix max of a
__device__ float g_nl[B_ * NH_ * S_];               // exp(-(cum+rm))

// =====================================================================
// Kernel 1: gate partial GEMM.  grid (32 row-tiles, 12 e-chunks), 256 thr
// per thread: 2 rows x 4 heads, f32x2 FMAs, float4 W reads
// =====================================================================
__global__ __launch_bounds__(256) void gates_partial_k(
    const float* __restrict__ q, const float* __restrict__ k,
    const float* __restrict__ v,
    const float* __restrict__ Wi, const float* __restrict__ Wf)
{
    __shared__ float Xs[64 * 65];
    __shared__ float Ws[64 * 32];
    const int rt = blockIdx.x;          // 0..31
    const int ec = blockIdx.y;          // 0..11
    const int b  = rt >> 4;
    const int s0 = (rt & 15) << 6;
    const int t  = threadIdx.x;
    const int rgrp = t >> 3;            // rows rgrp*2, rgrp*2+1
    const int hgrp = t & 7;             // heads hgrp*4 .. +3

    unsigned long long acc2[2][2] = {};

    for (int sub = 0; sub < 8; ++sub) {
        const int e0 = ec * ECH + sub * 64;
        const float* xp = (e0 < E_) ? q : (e0 < 2 * E_) ? k : v;
        const int col0 = e0 & (E_ - 1);
        __syncthreads();
        for (int i = t; i < 64 * 64; i += 256) {
            int r = i >> 6, ee = i & 63;
            Xs[r * 65 + ee] = xp[((size_t)(b * S_ + s0 + r)) * E_ + col0 + ee];
        }
        for (int i = t; i < 64 * 32; i += 256) {
            int ee = i >> 5, hh = i & 31;
            int eg = e0 + ee;
            Ws[ee * 32 + hh] = (hh < 16) ? Wi[eg * 16 + hh] : Wf[eg * 16 + (hh - 16)];
        }
        __syncthreads();
        #pragma unroll 8
        for (int ee = 0; ee < 64; ++ee) {
            unsigned long long xp2[2];
            #pragma unroll
            for (int m = 0; m < 2; ++m) {
                float xv = Xs[(rgrp * 2 + m) * 65 + ee];
                PACK2(xp2[m], xv);
            }
            ulonglong2 wv = *(const ulonglong2*)(Ws + ee * 32 + hgrp * 4);
            #pragma unroll
            for (int m = 0; m < 2; ++m) {
                FMA2(acc2[m][0], xp2[m], wv.x);
                FMA2(acc2[m][1], xp2[m], wv.y);
            }
        }
    }
    #pragma unroll
    for (int m = 0; m < 2; ++m) {
        int s = s0 + rgrp * 2 + m;
        #pragma unroll
        for (int p = 0; p < 2; ++p) {
            float2 u = *(float2*)&acc2[m][p];
            #pragma unroll
            for (int hh = 0; hh < 2; ++hh) {
                int hcol = hgrp * 4 + p * 2 + hh;
                int gate = hcol >> 4;
                int hm   = hcol & 15;
                float val = hh ? u.y : u.x;
                g_part[((gate * NEC + ec) * (B_ * NH_) + b * NH_ + hm) * S_ + s] = val;
            }
        }
    }
}

// =====================================================================
// Kernel 2: reduce partials + logsigmoid + inclusive scans (sum, max)
// =====================================================================
__global__ __launch_bounds__(1024, 1) void scan_k(
    const float* __restrict__ bi, const float* __restrict__ bf)
{
    __shared__ float buf[1024];
    const int bh = blockIdx.x;
    const int t  = threadIdx.x;
    const int h  = bh & 15;

    float ig = bi[h], fg = bf[h];
    #pragma unroll
    for (int ec = 0; ec < NEC; ++ec) {
        ig += g_part[((0 * NEC + ec) * (B_ * NH_) + bh) * S_ + t];
        fg += g_part[((1 * NEC + ec) * (B_ * NH_) + bh) * S_ + t];
    }
    float lf = fminf(fg, 0.f) - log1pf(expf(-fabsf(fg)));

    float x = lf;
    buf[t] = x; __syncthreads();
    for (int off = 1; off < 1024; off <<= 1) {
        float y = (t >= off) ? buf[t - off] : 0.f;
        __syncthreads();
        x += y; buf[t] = x; __syncthreads();
    }
    float cum = x;
    float a = ig - cum;

    x = a;
    buf[t] = x; __syncthreads();
    for (int off = 1; off < 1024; off <<= 1) {
        float y = (t >= off) ? buf[t - off] : -3.4e38f;
        __syncthreads();
        x = fmaxf(x, y); buf[t] = x; __syncthreads();
    }
    float rm = x;

    g_a [bh * S_ + t] = a;
    g_rm[bh * S_ + t] = rm;
    g_nl[bh * S_ + t] = expf(-(cum + rm));
}

// =====================================================================
// Kernel 3: causal mLSTM attention, 64x64 tiles, f32x2 + cp.async pipeline
// =====================================================================
#define QLD 130
#define SLD 66
#define SM_FLOATS (64*QLD + 2*64*QLD + 2*64*128 + 64*SLD + 2*64 + 64 + 64 + 64)

__global__ __launch_bounds__(256, 1) void attn_k(
    const float* __restrict__ q, const float* __restrict__ k,
    const float* __restrict__ v, const float* __restrict__ lnsc,
    float* __restrict__ out)
{
    extern __shared__ float sm[];
    float* Qs  = sm;                       // 64 x 130
    float* Ks  = Qs + 64 * QLD;            // 2 x 64 x 130
    float* Vs  = Ks + 2 * 64 * QLD;        // 2 x 64 x 128
    float* Ss  = Vs + 2 * 64 * 128;        // 64 x 66
    float* aS  = Ss + 64 * SLD;            // 2 x 64
    float* rmS = aS + 2 * 64;
    float* nlS = rmS + 64;
    float* Cs  = nlS + 64;

    const int bh = blockIdx.x;
    const int b  = bh >> 4, h = bh & 15;
    const int ri = (int)gridDim.y - 1 - (int)blockIdx.y;  // big tiles first
    const int i0 = ri << 6;
    const int t  = threadIdx.x;
    const float scale = 0.08838834764831845f;  // 1/sqrt(128)

    // ---- load Q tile (float2, stride 130) + per-row stats ----
    {
        size_t baseq = ((size_t)(b * S_ + i0)) * E_ + h * DH_;
        for (int i = t; i < 64 * 64; i += 256) {
            int r = i >> 6, d2 = (i & 63) * 2;
            *(float2*)(Qs + r * QLD + d2) = *(const float2*)(q + baseq + (size_t)r * E_ + d2);
        }
        if (t < 64) {
            rmS[t] = g_rm[bh * S_ + i0 + t];
            nlS[t] = g_nl[bh * S_ + i0 + t];
            Cs[t]  = 0.f;
        }
    }

    // ---- prefetch helper (inlined by macro-ish lambda) ----
    auto prefetch = [&](int buf, int j0) {
        float* Kb = Ks + buf * 64 * QLD;
        float* Vb = Vs + buf * 64 * 128;
        const float* kbase = k + ((size_t)(b * S_ + j0)) * E_ + h * DH_;
        const float* vbase = v + ((size_t)(b * S_ + j0)) * E_ + h * DH_;
        // V: 64x128 floats as 16B chunks
        #pragma unroll
        for (int c = 0; c < 8; ++c) {
            int idx = t + c * 256;
            int r = idx >> 5, d4 = (idx & 31) * 4;
            cpa16((uint32_t)__cvta_generic_to_shared(Vb + r * 128 + d4),
                  vbase + (size_t)r * E_ + d4);
        }
        // K: 64x128 floats as 8B chunks (stride 130)
        #pragma unroll
        for (int c = 0; c < 16; ++c) {
            int idx = t + c * 256;
            int r = idx >> 6, d2 = (idx & 63) * 2;
            cpa8((uint32_t)__cvta_generic_to_shared(Kb + r * QLD + d2),
                 kbase + (size_t)r * E_ + d2);
        }
        if (t < 16)
            cpa16((uint32_t)__cvta_generic_to_shared(aS + buf * 64 + t * 4),
                  g_a + bh * S_ + j0 + t * 4);
        cpa_commit();
    };

    prefetch(0, 0);

    unsigned long long acc2[8][2] = {};           // AV accumulators (d pairs)
    const int w  = t >> 5, l  = t & 31;           // AV/output mapping
    const int rg = t >> 4, cg = t & 15;           // score mapping (rows rg+16m, cols cg+16n)

    for (int jt = 0; jt <= ri; ++jt) {
        const int j0 = jt << 6;
        const int buf = jt & 1;
        if (jt < ri) {
            prefetch(buf ^ 1, j0 + 64);
            asm volatile("cp.async.wait_group 1;");
        } else {
            asm volatile("cp.async.wait_group 0;");
        }
        __syncthreads();   // K/V/a ready; prev AV readers done

        const float* Kb = Ks + buf * 64 * QLD;
        const float* ab = aS + buf * 64;

        // ---- scores: rows rg+16m, cols cg+16n, f32x2 along kk ----
        unsigned long long s2[4][4] = {};
        #pragma unroll 4
        for (int kk = 0; kk < DH_; kk += 2) {
            unsigned long long qv2[4], kv2[4];
            #pragma unroll
            for (int m = 0; m < 4; ++m)
                qv2[m] = *(const unsigned long long*)(Qs + (rg + 16 * m) * QLD + kk);
            #pragma unroll
            for (int n = 0; n < 4; ++n)
                kv2[n] = *(const unsigned long long*)(Kb + (cg + 16 * n) * QLD + kk);
            #pragma unroll
            for (int m = 0; m < 4; ++m)
                #pragma unroll
                for (int n = 0; n < 4; ++n)
                    FMA2(s2[m][n], qv2[m], kv2[n]);
        }
        #pragma unroll
        for (int m = 0; m < 4; ++m) {
            const int r = rg + 16 * m;
            const int iglob = i0 + r;
            float rsum = 0.f;
            #pragma unroll
            for (int n = 0; n < 4; ++n) {
                const int c = cg + 16 * n;
                const int jglob = j0 + c;
                float2 u = *(float2*)&s2[m][n];
                float sacc = u.x + u.y;
                float p = (jglob <= iglob) ? __expf(ab[c] - rmS[r]) : 0.f;
                float cval = sacc * scale * p;
                Ss[r * SLD + c] = cval;
                rsum += cval;
            }
            #pragma unroll
            for (int off = 8; off > 0; off >>= 1)
                rsum += __shfl_down_sync(0xffffffffu, rsum, off, 16);
            if (cg == 0) Cs[r] += rsum;
        }
        __syncthreads();   // Ss ready

        // ---- AV: acc[8 rows][4 d] per thread, f32x2 along d ----
        const float* Vb = Vs + buf * 64 * 128;
        #pragma unroll 2
        for (int j = 0; j < 64; ++j) {
            ulonglong2 vv = *(const ulonglong2*)(Vb + j * 128 + l * 4);
            #pragma unroll
            for (int rr = 0; rr < 8; ++rr) {
                float sv = Ss[(w * 8 + rr) * SLD + j];
                unsigned long long svp;
                PACK2(svp, sv);
                FMA2(acc2[rr][0], svp, vv.x);
                FMA2(acc2[rr][1], svp, vv.y);
            }
        }
        __syncthreads();   // AV done; buffers/Ss free
    }

    // ---- epilogue: normalizer + per-head LayerNorm + store ----
    const int dbase = l * 4;
    float ln0 = lnsc[h * DH_ + dbase + 0];
    float ln1 = lnsc[h * DH_ + dbase + 1];
    float ln2 = lnsc[h * DH_ + dbase + 2];
    float ln3 = lnsc[h * DH_ + dbase + 3];
    #pragma unroll
    for (int rr = 0; rr < 8; ++rr) {
        const int r = w * 8 + rr;
        float denom = fmaxf(fabsf(Cs[r]), nlS[r]) + EPS_;
        float inv = 1.f / denom;
        float2 a0 = *(float2*)&acc2[rr][0];
        float2 a1 = *(float2*)&acc2[rr][1];
        float hv[4] = {a0.x * inv, a0.y * inv, a1.x * inv, a1.y * inv};
        float s = hv[0] + hv[1] + hv[2] + hv[3];
        #pragma unroll
        for (int off = 16; off > 0; off >>= 1) s += __shfl_xor_sync(0xffffffffu, s, off);
        float mu = s * (1.f / 128.f);
        float vs = 0.f;
        #pragma unroll
        for (int dd = 0; dd < 4; ++dd) { float d0 = hv[dd] - mu; vs += d0 * d0; }
        #pragma unroll
        for (int off = 16; off > 0; off >>= 1) vs += __shfl_xor_sync(0xffffffffu, vs, off);
        float rstd = rsqrtf(vs * (1.f / 128.f) + EPS_);
        float4 o;
        o.x = (hv[0] - mu) * rstd * ln0;
        o.y = (hv[1] - mu) * rstd * ln1;
        o.z = (hv[2] - mu) * rstd * ln2;
        o.w = (hv[3] - mu) * rstd * ln3;
        *(float4*)(out + ((size_t)(b * S_ + i0 + r)) * E_ + h * DH_ + dbase) = o;
    }
}

// =====================================================================
extern "C" void kernel_launch(void* const* d_in, const int* in_sizes, int n_in,
                              void* d_out, int out_size)
{
    const float* q  = (const float*)d_in[0];
    const float* k  = (const float*)d_in[1];
    const float* v  = (const float*)d_in[2];
    const float* Wi = (const float*)d_in[3];
    const float* bi = (const float*)d_in[4];
    const float* Wf = (const float*)d_in[5];
    const float* bf = (const float*)d_in[6];
    const float* ln = (const float*)d_in[7];
    float* out = (float*)d_out;

    cudaFuncSetAttribute(attn_k, cudaFuncAttributeMaxDynamicSharedMemorySize,
                         SM_FLOATS * (int)sizeof(float));

    gates_partial_k<<<dim3(32, NEC), 256>>>(q, k, v, Wi, Wf);
    scan_k<<<B_ * NH_, 1024>>>(bi, bf);
    attn_k<<<dim3(B_ * NH_, 16), 256, SM_FLOATS * sizeof(float)>>>(q, k, v, ln, out);
}

// round 5
// speedup vs baseline: 1.0018x; 1.0018x over previous
#include <cuda_runtime.h>
#include <math.h>
#include <stdint.h>

#define B_   2
#define S_   1024
#define E_   2048
#define NH_  16
#define DH_  128
#define EPS_ 1e-6f
#define NEC  12          // e-chunks for gates GEMM split-K
#define ECH  512         // 6144 / 12

// ---------------- f32x2 helpers (Blackwell packed fp32) ----------------
#define FMA2(d, a, b)  asm("fma.rn.f32x2 %0, %1, %2, %0;" : "+l"(d) : "l"(a), "l"(b))
#define PACK2(d, x)    asm("mov.b64 %0, {%1, %1};" : "=l"(d) : "f"(x))

__device__ __forceinline__ void cpa16(uint32_t dst, const void* src) {
    asm volatile("cp.async.ca.shared.global [%0], [%1], 16;" :: "r"(dst), "l"(src));
}
__device__ __forceinline__ void cpa8(uint32_t dst, const void* src) {
    asm volatile("cp.async.ca.shared.global [%0], [%1], 8;" :: "r"(dst), "l"(src));
}
__device__ __forceinline__ void cpa_commit() { asm volatile("cp.async.commit_group;"); }

// -------- device scratch (no allocations allowed) --------
__device__ float g_part[2 * NEC * B_ * NH_ * S_];   // gate partial sums
__device__ float g_a [B_ * NH_ * S_];               // a[j] = ig[j] - cum[j]
__device__ float g_rm[B_ * NH_ * S_];               // prefix max of a
__device__ float g_nl[B_ * NH_ * S_];               // exp(-(cum+rm))

// =====================================================================
// Kernel 1: gate partial GEMM.  grid (32 row-tiles, 12 e-chunks), 256 thr
// per thread: 2 rows x 4 heads, f32x2 FMAs, float4 W reads
// =====================================================================
__global__ __launch_bounds__(256) void gates_partial_k(
    const float* __restrict__ q, const float* __restrict__ k,
    const float* __restrict__ v,
    const float* __restrict__ Wi, const float* __restrict__ Wf)
{
    __shared__ float Xs[64 * 65];
    __shared__ float Ws[64 * 32];
    const int rt = blockIdx.x;          // 0..31
    const int ec = blockIdx.y;          // 0..11
    const int b  = rt >> 4;
    const int s0 = (rt & 15) << 6;
    const int t  = threadIdx.x;
    const int rgrp = t >> 3;            // rows rgrp*2, rgrp*2+1
    const int hgrp = t & 7;             // heads hgrp*4 .. +3

    unsigned long long acc2[2][2] = {};

    for (int sub = 0; sub < 8; ++sub) {
        const int e0 = ec * ECH + sub * 64;
        const float* xp = (e0 < E_) ? q : (e0 < 2 * E_) ? k : v;
        const int col0 = e0 & (E_ - 1);
        __syncthreads();
        for (int i = t; i < 64 * 64; i += 256) {
            int r = i >> 6, ee = i & 63;
            Xs[r * 65 + ee] = xp[((size_t)(b * S_ + s0 + r)) * E_ + col0 + ee];
        }
        for (int i = t; i < 64 * 32; i += 256) {
            int ee = i >> 5, hh = i & 31;
            int eg = e0 + ee;
            Ws[ee * 32 + hh] = (hh < 16) ? Wi[eg * 16 + hh] : Wf[eg * 16 + (hh - 16)];
        }
        __syncthreads();
        #pragma unroll 8
        for (int ee = 0; ee < 64; ++ee) {
            unsigned long long xp2[2];
            #pragma unroll
            for (int m = 0; m < 2; ++m) {
                float xv = Xs[(rgrp * 2 + m) * 65 + ee];
                PACK2(xp2[m], xv);
            }
            ulonglong2 wv = *(const ulonglong2*)(Ws + ee * 32 + hgrp * 4);
            #pragma unroll
            for (int m = 0; m < 2; ++m) {
                FMA2(acc2[m][0], xp2[m], wv.x);
                FMA2(acc2[m][1], xp2[m], wv.y);
            }
        }
    }
    #pragma unroll
    for (int m = 0; m < 2; ++m) {
        int s = s0 + rgrp * 2 + m;
        #pragma unroll
        for (int p = 0; p < 2; ++p) {
            float2 u = *(float2*)&acc2[m][p];
            #pragma unroll
            for (int hh = 0; hh < 2; ++hh) {
                int hcol = hgrp * 4 + p * 2 + hh;
                int gate = hcol >> 4;
                int hm   = hcol & 15;
                float val = hh ? u.y : u.x;
                g_part[((gate * NEC + ec) * (B_ * NH_) + b * NH_ + hm) * S_ + s] = val;
            }
        }
    }
}

// =====================================================================
// Kernel 2: reduce partials + logsigmoid + inclusive scans (sum, max)
// =====================================================================
__global__ __launch_bounds__(1024, 1) void scan_k(
    const float* __restrict__ bi, const float* __restrict__ bf)
{
    __shared__ float buf[1024];
    const int bh = blockIdx.x;
    const int t  = threadIdx.x;
    const int h  = bh & 15;

    float ig = bi[h], fg = bf[h];
    #pragma unroll
    for (int ec = 0; ec < NEC; ++ec) {
        ig += g_part[((0 * NEC + ec) * (B_ * NH_) + bh) * S_ + t];
        fg += g_part[((1 * NEC + ec) * (B_ * NH_) + bh) * S_ + t];
    }
    float lf = fminf(fg, 0.f) - log1pf(expf(-fabsf(fg)));

    float x = lf;
    buf[t] = x; __syncthreads();
    for (int off = 1; off < 1024; off <<= 1) {
        float y = (t >= off) ? buf[t - off] : 0.f;
        __syncthreads();
        x += y; buf[t] = x; __syncthreads();
    }
    float cum = x;
    float a = ig - cum;

    x = a;
    buf[t] = x; __syncthreads();
    for (int off = 1; off < 1024; off <<= 1) {
        float y = (t >= off) ? buf[t - off] : -3.4e38f;
        __syncthreads();
        x = fmaxf(x, y); buf[t] = x; __syncthreads();
    }
    float rm = x;

    g_a [bh * S_ + t] = a;
    g_rm[bh * S_ + t] = rm;
    g_nl[bh * S_ + t] = expf(-(cum + rm));
}

// =====================================================================
// Kernel 3: causal mLSTM attention, 64x64 tiles, f32x2 + cp.async pipeline
// =====================================================================
#define QLD 130
#define SLD 66
#define SM_FLOATS (64*QLD + 2*64*QLD + 2*64*128 + 64*SLD + 2*64 + 64 + 64 + 64)

__global__ __launch_bounds__(256, 1) void attn_k(
    const float* __restrict__ q, const float* __restrict__ k,
    const float* __restrict__ v, const float* __restrict__ lnsc,
    float* __restrict__ out)
{
    extern __shared__ float sm[];
    float* Qs  = sm;                       // 64 x 130
    float* Ks  = Qs + 64 * QLD;            // 2 x 64 x 130
    float* Vs  = Ks + 2 * 64 * QLD;        // 2 x 64 x 128
    float* Ss  = Vs + 2 * 64 * 128;        // 64 x 66
    float* aS  = Ss + 64 * SLD;            // 2 x 64
    float* rmS = aS + 2 * 64;
    float* nlS = rmS + 64;
    float* Cs  = nlS + 64;

    const int bh = blockIdx.x;
    const int b  = bh >> 4, h = bh & 15;
    const int ri = (int)gridDim.y - 1 - (int)blockIdx.y;  // big tiles first
    const int i0 = ri << 6;
    const int t  = threadIdx.x;
    const float scale = 0.08838834764831845f;  // 1/sqrt(128)

    // ---- load Q tile (float2, stride 130) + per-row stats ----
    {
        size_t baseq = ((size_t)(b * S_ + i0)) * E_ + h * DH_;
        for (int i = t; i < 64 * 64; i += 256) {
            int r = i >> 6, d2 = (i & 63) * 2;
            *(float2*)(Qs + r * QLD + d2) = *(const float2*)(q + baseq + (size_t)r * E_ + d2);
        }
        if (t < 64) {
            rmS[t] = g_rm[bh * S_ + i0 + t];
            nlS[t] = g_nl[bh * S_ + i0 + t];
            Cs[t]  = 0.f;
        }
    }

    // ---- prefetch helper (inlined by macro-ish lambda) ----
    auto prefetch = [&](int buf, int j0) {
        float* Kb = Ks + buf * 64 * QLD;
        float* Vb = Vs + buf * 64 * 128;
        const float* kbase = k + ((size_t)(b * S_ + j0)) * E_ + h * DH_;
        const float* vbase = v + ((size_t)(b * S_ + j0)) * E_ + h * DH_;
        // V: 64x128 floats as 16B chunks
        #pragma unroll
        for (int c = 0; c < 8; ++c) {
            int idx = t + c * 256;
            int r = idx >> 5, d4 = (idx & 31) * 4;
            cpa16((uint32_t)__cvta_generic_to_shared(Vb + r * 128 + d4),
                  vbase + (size_t)r * E_ + d4);
        }
        // K: 64x128 floats as 8B chunks (stride 130)
        #pragma unroll
        for (int c = 0; c < 16; ++c) {
            int idx = t + c * 256;
            int r = idx >> 6, d2 = (idx & 63) * 2;
            cpa8((uint32_t)__cvta_generic_to_shared(Kb + r * QLD + d2),
                 kbase + (size_t)r * E_ + d2);
        }
        if (t < 16)
            cpa16((uint32_t)__cvta_generic_to_shared(aS + buf * 64 + t * 4),
                  g_a + bh * S_ + j0 + t * 4);
        cpa_commit();
    };

    prefetch(0, 0);

    unsigned long long acc2[8][2] = {};           // AV accumulators (d pairs)
    const int w  = t >> 5, l  = t & 31;           // AV/output mapping
    const int rg = t >> 4, cg = t & 15;           // score mapping (rows rg+16m, cols cg+16n)

    for (int jt = 0; jt <= ri; ++jt) {
        const int j0 = jt << 6;
        const int buf = jt & 1;
        if (jt < ri) {
            prefetch(buf ^ 1, j0 + 64);
            asm volatile("cp.async.wait_group 1;");
        } else {
            asm volatile("cp.async.wait_group 0;");
        }
        __syncthreads();   // K/V/a ready; prev AV readers done

        const float* Kb = Ks + buf * 64 * QLD;
        const float* ab = aS + buf * 64;

        // ---- scores: rows rg+16m, cols cg+16n, f32x2 along kk ----
        unsigned long long s2[4][4] = {};
        #pragma unroll 4
        for (int kk = 0; kk < DH_; kk += 2) {
            unsigned long long qv2[4], kv2[4];
            #pragma unroll
            for (int m = 0; m < 4; ++m)
                qv2[m] = *(const unsigned long long*)(Qs + (rg + 16 * m) * QLD + kk);
            #pragma unroll
            for (int n = 0; n < 4; ++n)
                kv2[n] = *(const unsigned long long*)(Kb + (cg + 16 * n) * QLD + kk);
            #pragma unroll
            for (int m = 0; m < 4; ++m)
                #pragma unroll
                for (int n = 0; n < 4; ++n)
                    FMA2(s2[m][n], qv2[m], kv2[n]);
        }
        #pragma unroll
        for (int m = 0; m < 4; ++m) {
            const int r = rg + 16 * m;
            const int iglob = i0 + r;
            float rsum = 0.f;
            #pragma unroll
            for (int n = 0; n < 4; ++n) {
                const int c = cg + 16 * n;
                const int jglob = j0 + c;
                float2 u = *(float2*)&s2[m][n];
                float sacc = u.x + u.y;
                float p = (jglob <= iglob) ? __expf(ab[c] - rmS[r]) : 0.f;
                float cval = sacc * scale * p;
                Ss[r * SLD + c] = cval;
                rsum += cval;
            }
            #pragma unroll
            for (int off = 8; off > 0; off >>= 1)
                rsum += __shfl_down_sync(0xffffffffu, rsum, off, 16);
            if (cg == 0) Cs[r] += rsum;
        }
        __syncthreads();   // Ss ready

        // ---- AV: acc[8 rows][4 d] per thread, f32x2 along d ----
        const float* Vb = Vs + buf * 64 * 128;
        #pragma unroll 2
        for (int j = 0; j < 64; ++j) {
            ulonglong2 vv = *(const ulonglong2*)(Vb + j * 128 + l * 4);
            #pragma unroll
            for (int rr = 0; rr < 8; ++rr) {
                float sv = Ss[(w * 8 + rr) * SLD + j];
                unsigned long long svp;
                PACK2(svp, sv);
                FMA2(acc2[rr][0], svp, vv.x);
                FMA2(acc2[rr][1], svp, vv.y);
            }
        }
        __syncthreads();   // AV done; buffers/Ss free
    }

    // ---- epilogue: normalizer + per-head LayerNorm + store ----
    const int dbase = l * 4;
    float ln0 = lnsc[h * DH_ + dbase + 0];
    float ln1 = lnsc[h * DH_ + dbase + 1];
    float ln2 = lnsc[h * DH_ + dbase + 2];
    float ln3 = lnsc[h * DH_ + dbase + 3];
    #pragma unroll
    for (int rr = 0; rr < 8; ++rr) {
        const int r = w * 8 + rr;
        float denom = fmaxf(fabsf(Cs[r]), nlS[r]) + EPS_;
        float inv = 1.f / denom;
        float2 a0 = *(float2*)&acc2[rr][0];
        float2 a1 = *(float2*)&acc2[rr][1];
        float hv[4] = {a0.x * inv, a0.y * inv, a1.x * inv, a1.y * inv};
        float s = hv[0] + hv[1] + hv[2] + hv[3];
        #pragma unroll
        for (int off = 16; off > 0; off >>= 1) s += __shfl_xor_sync(0xffffffffu, s, off);
        float mu = s * (1.f / 128.f);
        float vs = 0.f;
        #pragma unroll
        for (int dd = 0; dd < 4; ++dd) { float d0 = hv[dd] - mu; vs += d0 * d0; }
        #pragma unroll
        for (int off = 16; off > 0; off >>= 1) vs += __shfl_xor_sync(0xffffffffu, vs, off);
        float rstd = rsqrtf(vs * (1.f / 128.f) + EPS_);
        float4 o;
        o.x = (hv[0] - mu) * rstd * ln0;
        o.y = (hv[1] - mu) * rstd * ln1;
        o.z = (hv[2] - mu) * rstd * ln2;
        o.w = (hv[3] - mu) * rstd * ln3;
        *(float4*)(out + ((size_t)(b * S_ + i0 + r)) * E_ + h * DH_ + dbase) = o;
    }
}

// =====================================================================
extern "C" void kernel_launch(void* const* d_in, const int* in_sizes, int n_in,
                              void* d_out, int out_size)
{
    const float* q  = (const float*)d_in[0];
    const float* k  = (const float*)d_in[1];
    const float* v  = (const float*)d_in[2];
    const float* Wi = (const float*)d_in[3];
    const float* bi = (const float*)d_in[4];
    const float* Wf = (const float*)d_in[5];
    const float* bf = (const float*)d_in[6];
    const float* ln = (const float*)d_in[7];
    float* out = (float*)d_out;

    cudaFuncSetAttribute(attn_k, cudaFuncAttributeMaxDynamicSharedMemorySize,
                         SM_FLOATS * (int)sizeof(float));

    gates_partial_k<<<dim3(32, NEC), 256>>>(q, k, v, Wi, Wf);
    scan_k<<<B_ * NH_, 1024>>>(bi, bf);
    attn_k<<<dim3(B_ * NH_, 16), 256, SM_FLOATS * sizeof(float)>>>(q, k, v, ln, out);
}

// round 7
// speedup vs baseline: 2.4658x; 2.4613x over previous
#include <cuda_runtime.h>
#include <cuda_bf16.h>
#include <math.h>
#include <stdint.h>

#define B_   2
#define S_   1024
#define E_   2048
#define NH_  16
#define DH_  128
#define EPS_ 1e-6f
#define NEC  12
#define ECH  512

#define FMA2(d, a, b)  asm("fma.rn.f32x2 %0, %1, %2, %0;" : "+l"(d) : "l"(a), "l"(b))
#define PACK2(d, x)    asm("mov.b64 %0, {%1, %1};" : "=l"(d) : "f"(x))

// ---------------- warp-MMA helpers (sm_80-era PTX: safe under compute_103) ----------------
static __device__ __forceinline__ uint32_t pack_bf2(float x0, float x1) {
    uint32_t r; asm("cvt.rn.bf16x2.f32 %0, %1, %2;" : "=r"(r) : "f"(x1), "f"(x0)); return r;
}
static __device__ __forceinline__ float lo_f(uint32_t p) { return __uint_as_float(p << 16); }
static __device__ __forceinline__ float hi_f(uint32_t p) { return __uint_as_float(p & 0xffff0000u); }

#define LDSM4(r, a) \
    asm volatile("ldmatrix.sync.aligned.m8n8.x4.shared.b16 {%0,%1,%2,%3}, [%4];" \
        : "=r"((r)[0]), "=r"((r)[1]), "=r"((r)[2]), "=r"((r)[3]) : "r"(a))
#define LDSM4T(r, a) \
    asm volatile("ldmatrix.sync.aligned.m8n8.x4.trans.shared.b16 {%0,%1,%2,%3}, [%4];" \
        : "=r"((r)[0]), "=r"((r)[1]), "=r"((r)[2]), "=r"((r)[3]) : "r"(a))

static __device__ __forceinline__ void mma16816(float* c, const uint32_t* a, const uint32_t* b) {
    asm volatile("mma.sync.aligned.m16n8k16.row.col.f32.bf16.bf16.f32 "
        "{%0,%1,%2,%3}, {%4,%5,%6,%7}, {%8,%9}, {%0,%1,%2,%3};"
        : "+f"(c[0]), "+f"(c[1]), "+f"(c[2]), "+f"(c[3])
        : "r"(a[0]), "r"(a[1]), "r"(a[2]), "r"(a[3]), "r"(b[0]), "r"(b[1]));
}

__device__ float g_part[2 * NEC * B_ * NH_ * S_];
__device__ float g_a [B_ * NH_ * S_];
__device__ float g_rm[B_ * NH_ * S_];
__device__ float g_nl[B_ * NH_ * S_];

// ============== Kernel 1: gates (unchanged, known-good) ==============
__global__ __launch_bounds__(256) void gates_partial_k(
    const float* __restrict__ q, const float* __restrict__ k, const float* __restrict__ v,
    const float* __restrict__ Wi, const float* __restrict__ Wf)
{
    __shared__ float Xs[64 * 65];
    __shared__ float Ws[64 * 32];
    const int rt = blockIdx.x, ec = blockIdx.y;
    const int b = rt >> 4, s0 = (rt & 15) << 6, t = threadIdx.x;
    const int rgrp = t >> 3, hgrp = t & 7;
    unsigned long long acc2[2][2] = {};
    for (int sub = 0; sub < 8; ++sub) {
        const int e0 = ec * ECH + sub * 64;
        const float* xp = (e0 < E_) ? q : (e0 < 2 * E_) ? k : v;
        const int col0 = e0 & (E_ - 1);
        __syncthreads();
        for (int i = t; i < 64 * 64; i += 256) {
            int r = i >> 6, ee = i & 63;
            Xs[r * 65 + ee] = xp[((size_t)(b * S_ + s0 + r)) * E_ + col0 + ee];
        }
        for (int i = t; i < 64 * 32; i += 256) {
            int ee = i >> 5, hh = i & 31, eg = e0 + ee;
            Ws[ee * 32 + hh] = (hh < 16) ? Wi[eg * 16 + hh] : Wf[eg * 16 + (hh - 16)];
        }
        __syncthreads();
        #pragma unroll 8
        for (int ee = 0; ee < 64; ++ee) {
            unsigned long long xp2[2];
            #pragma unroll
            for (int m = 0; m < 2; ++m) { float xv = Xs[(rgrp * 2 + m) * 65 + ee]; PACK2(xp2[m], xv); }
            ulonglong2 wv = *(const ulonglong2*)(Ws + ee * 32 + hgrp * 4);
            #pragma unroll
            for (int m = 0; m < 2; ++m) { FMA2(acc2[m][0], xp2[m], wv.x); FMA2(acc2[m][1], xp2[m], wv.y); }
        }
    }
    #pragma unroll
    for (int m = 0; m < 2; ++m) {
        int s = s0 + rgrp * 2 + m;
        #pragma unroll
        for (int p = 0; p < 2; ++p) {
            float2 u = *(float2*)&acc2[m][p];
            #pragma unroll
            for (int hh = 0; hh < 2; ++hh) {
                int hcol = hgrp * 4 + p * 2 + hh;
                g_part[(((hcol >> 4) * NEC + ec) * (B_ * NH_) + b * NH_ + (hcol & 15)) * S_ + s] = hh ? u.y : u.x;
            }
        }
    }
}

// ============== Kernel 2: scans (unchanged) ==============
__global__ __launch_bounds__(1024, 1) void scan_k(const float* __restrict__ bi, const float* __restrict__ bf)
{
    __shared__ float buf[1024];
    const int bh = blockIdx.x, t = threadIdx.x, h = bh & 15;
    float ig = bi[h], fg = bf[h];
    #pragma unroll
    for (int ec = 0; ec < NEC; ++ec) {
        ig += g_part[((0 * NEC + ec) * (B_ * NH_) + bh) * S_ + t];
        fg += g_part[((1 * NEC + ec) * (B_ * NH_) + bh) * S_ + t];
    }
    float lf = fminf(fg, 0.f) - log1pf(expf(-fabsf(fg)));
    float x = lf;
    buf[t] = x; __syncthreads();
    for (int off = 1; off < 1024; off <<= 1) {
        float y = (t >= off) ? buf[t - off] : 0.f; __syncthreads();
        x += y; buf[t] = x; __syncthreads();
    }
    float cum = x, a = ig - cum;
    x = a; buf[t] = x; __syncthreads();
    for (int off = 1; off < 1024; off <<= 1) {
        float y = (t >= off) ? buf[t - off] : -3.4e38f; __syncthreads();
        x = fmaxf(x, y); buf[t] = x; __syncthreads();
    }
    g_a [bh * S_ + t] = a;
    g_rm[bh * S_ + t] = x;
    g_nl[bh * S_ + t] = expf(-(cum + x));
}

// ============== Kernel 3: HMMA bf16 attention ==============
// Row stride 136 halves (272B) -> 4-bank step, conflict-free LDSM.
#define LDH  136
// SMEM byte offsets
#define SM_QHI 0
#define SM_QLO 34816
#define SM_KHI 69632
#define SM_KLO 87040
#define SM_VHI 104448
#define SM_VLO 121856
#define SM_AS  139264
#define SM_RMS 139520
#define SM_ERS 140032
#define SM_WCS 140544
#define SM_BYTES 140800

__global__ __launch_bounds__(256, 1) void attn_k(
    const float* __restrict__ q, const float* __restrict__ k,
    const float* __restrict__ v, const float* __restrict__ lnsc,
    float* __restrict__ out)
{
    extern __shared__ char smc[];
    const uint32_t smb = (uint32_t)__cvta_generic_to_shared(smc);
    float* aS  = (float*)(smc + SM_AS);
    float* rmS = (float*)(smc + SM_RMS);
    float* erS = (float*)(smc + SM_ERS);
    float* wcS = (float*)(smc + SM_WCS);

    const int bh = blockIdx.x;
    const int b  = bh >> 4, h = bh & 15;
    const int ri = 7 - (int)blockIdx.y;      // heavy CTAs first
    const int i0 = ri << 7;
    const int t  = threadIdx.x;
    const int w  = t >> 5, lane = t & 31;
    const int gid = lane >> 2, tig = lane & 3;
    const float scale = 0.08838834764831845f;

    // ---- Q load: fold scale, bf16 hi/lo split into padded row-major smem ----
    {
        const float* qb = q + ((size_t)(b * S_ + i0)) * E_ + h * DH_;
        #pragma unroll
        for (int it = 0; it < 16; ++it) {
            int idx = t + it * 256;
            int r = idx >> 5, d4 = (idx & 31) * 4;
            float4 x = *(const float4*)(qb + (size_t)r * E_ + d4);
            x.x *= scale; x.y *= scale; x.z *= scale; x.w *= scale;
            uint32_t h01 = pack_bf2(x.x, x.y), h23 = pack_bf2(x.z, x.w);
            uint32_t l01 = pack_bf2(x.x - lo_f(h01), x.y - hi_f(h01));
            uint32_t l23 = pack_bf2(x.z - lo_f(h23), x.w - hi_f(h23));
            uint32_t bo = (uint32_t)(r * LDH + d4) * 2;
            *(uint2*)(smc + SM_QHI + bo) = make_uint2(h01, h23);
            *(uint2*)(smc + SM_QLO + bo) = make_uint2(l01, l23);
        }
        if (t < 128) rmS[t] = g_rm[bh * S_ + i0 + t];
    }
    __syncthreads();

    // ---- cache Q fragments in registers (A-operand layout) ----
    uint32_t qh[8][4], ql[8][4];
    {
        uint32_t rowq = (uint32_t)(w * 16 + (lane & 7) + 8 * ((lane >> 3) & 1));
        #pragma unroll
        for (int kk = 0; kk < 8; ++kk) {
            uint32_t off = (rowq * LDH + kk * 16 + 8 * (lane >> 4)) * 2;
            LDSM4(qh[kk], smb + SM_QHI + off);
            LDSM4(ql[kk], smb + SM_QLO + off);
        }
    }

    float hacc[16][4];
    #pragma unroll
    for (int n = 0; n < 16; ++n)
        #pragma unroll
        for (int e = 0; e < 4; ++e) hacc[n][e] = 0.f;
    float suma = 0.f, sumb = 0.f;

    const int rowa = i0 + w * 16 + gid;       // global row of acc elems 0,1
    const int rowb = rowa + 8;                // global row of acc elems 2,3
    const int nj = 2 * ri + 2;

    for (int jt = 0; jt < nj; ++jt) {
        const int j0 = jt << 6;
        __syncthreads();    // prev tile compute done before overwriting K/V/wc/er
        // ---- K,V tiles: split hi/lo ----
        {
            const float* kb = k + ((size_t)(b * S_ + j0)) * E_ + h * DH_;
            const float* vb = v + ((size_t)(b * S_ + j0)) * E_ + h * DH_;
            #pragma unroll
            for (int it = 0; it < 8; ++it) {
                int idx = t + it * 256;
                int r = idx >> 5, d4 = (idx & 31) * 4;
                uint32_t bo = (uint32_t)(r * LDH + d4) * 2;
                float4 x = *(const float4*)(kb + (size_t)r * E_ + d4);
                uint32_t h01 = pack_bf2(x.x, x.y), h23 = pack_bf2(x.z, x.w);
                uint32_t l01 = pack_bf2(x.x - lo_f(h01), x.y - hi_f(h01));
                uint32_t l23 = pack_bf2(x.z - lo_f(h23), x.w - hi_f(h23));
                *(uint2*)(smc + SM_KHI + bo) = make_uint2(h01, h23);
                *(uint2*)(smc + SM_KLO + bo) = make_uint2(l01, l23);
                float4 y = *(const float4*)(vb + (size_t)r * E_ + d4);
                uint32_t g01 = pack_bf2(y.x, y.y), g23 = pack_bf2(y.z, y.w);
                uint32_t m01 = pack_bf2(y.x - lo_f(g01), y.y - hi_f(g01));
                uint32_t m23 = pack_bf2(y.z - lo_f(g23), y.w - hi_f(g23));
                *(uint2*)(smc + SM_VHI + bo) = make_uint2(g01, g23);
                *(uint2*)(smc + SM_VLO + bo) = make_uint2(m01, m23);
            }
            if (t < 64) aS[t] = g_a[bh * S_ + j0 + t];
        }
        __syncthreads();
        // ---- exp tables: wc[c] = exp(a-m0); er[r] = exp(m0-rm) (clamped) ----
        if (t < 128) {
            float m0 = -3.4e38f;
            #pragma unroll 8
            for (int c = 0; c < 64; ++c) m0 = fmaxf(m0, aS[c]);
            if (t < 64) wcS[t] = __expf(aS[t] - m0);
            erS[t] = __expf(fminf(m0 - rmS[t], 80.f));
        }
        __syncthreads();

        // ---- QK: S = Q K^T (3 compensated MMAs) ----
        float sacc[8][4];
        #pragma unroll
        for (int n = 0; n < 8; ++n)
            #pragma unroll
            for (int e = 0; e < 4; ++e) sacc[n][e] = 0.f;
        {
            uint32_t rowk = (uint32_t)((lane & 7) + 8 * (lane >> 4));
            uint32_t colk = (uint32_t)(8 * ((lane >> 3) & 1));
            #pragma unroll
            for (int kk = 0; kk < 8; ++kk) {
                #pragma unroll
                for (int np = 0; np < 4; ++np) {
                    uint32_t off = ((np * 16 + rowk) * LDH + kk * 16 + colk) * 2;
                    uint32_t bhf[4], blf[4];
                    LDSM4(bhf, smb + SM_KHI + off);
                    LDSM4(blf, smb + SM_KLO + off);
                    mma16816(sacc[2 * np],     qh[kk], bhf);
                    mma16816(sacc[2 * np],     qh[kk], blf);
                    mma16816(sacc[2 * np],     ql[kk], bhf);
                    mma16816(sacc[2 * np + 1], qh[kk], bhf + 2);
                    mma16816(sacc[2 * np + 1], qh[kk], blf + 2);
                    mma16816(sacc[2 * np + 1], ql[kk], bhf + 2);
                }
            }
        }

        // ---- S -> P = S * wc[c] * er[r], causal mask, accumulate rowsums ----
        const float era = erS[w * 16 + gid];
        const float erb = erS[w * 16 + gid + 8];
        #pragma unroll
        for (int n = 0; n < 8; ++n) {
            const int cbase = n * 8 + 2 * tig;
            const int c0 = j0 + cbase, c1 = c0 + 1;
            const float w0 = wcS[cbase], w1 = wcS[cbase + 1];
            float p0 = (c0 <= rowa) ? sacc[n][0] * w0 * era : 0.f;
            float p1 = (c1 <= rowa) ? sacc[n][1] * w1 * era : 0.f;
            float p2 = (c0 <= rowb) ? sacc[n][2] * w0 * erb : 0.f;
            float p3 = (c1 <= rowb) ? sacc[n][3] * w1 * erb : 0.f;
            suma += p0 + p1; sumb += p2 + p3;
            sacc[n][0] = p0; sacc[n][1] = p1; sacc[n][2] = p2; sacc[n][3] = p3;
        }

        // ---- AV: H += P V (3 compensated MMAs); P fragments from registers ----
        {
            uint32_t rowv = (uint32_t)((lane & 7) + 8 * ((lane >> 3) & 1));
            uint32_t colv = (uint32_t)(8 * (lane >> 4));
            #pragma unroll
            for (int kk = 0; kk < 4; ++kk) {
                uint32_t pah[4], pal[4];
                pah[0] = pack_bf2(sacc[2*kk][0],   sacc[2*kk][1]);
                pah[1] = pack_bf2(sacc[2*kk][2],   sacc[2*kk][3]);
                pah[2] = pack_bf2(sacc[2*kk+1][0], sacc[2*kk+1][1]);
                pah[3] = pack_bf2(sacc[2*kk+1][2], sacc[2*kk+1][3]);
                pal[0] = pack_bf2(sacc[2*kk][0]   - lo_f(pah[0]), sacc[2*kk][1]   - hi_f(pah[0]));
                pal[1] = pack_bf2(sacc[2*kk][2]   - lo_f(pah[1]), sacc[2*kk][3]   - hi_f(pah[1]));
                pal[2] = pack_bf2(sacc[2*kk+1][0] - lo_f(pah[2]), sacc[2*kk+1][1] - hi_f(pah[2]));
                pal[3] = pack_bf2(sacc[2*kk+1][2] - lo_f(pah[3]), sacc[2*kk+1][3] - hi_f(pah[3]));
                #pragma unroll
                for (int np = 0; np < 8; ++np) {
                    uint32_t off = ((kk * 16 + rowv) * LDH + np * 16 + colv) * 2;
                    uint32_t bvh[4], bvl[4];
                    LDSM4T(bvh, smb + SM_VHI + off);
                    LDSM4T(bvl, smb + SM_VLO + off);
                    mma16816(hacc[2 * np],     pah, bvh);
                    mma16816(hacc[2 * np],     pah, bvl);
                    mma16816(hacc[2 * np],     pal, bvh);
                    mma16816(hacc[2 * np + 1], pah, bvh + 2);
                    mma16816(hacc[2 * np + 1], pah, bvl + 2);
                    mma16816(hacc[2 * np + 1], pal, bvh + 2);
                }
            }
        }
    }

    // ---- epilogue: normalizer + per-head LayerNorm + store ----
    suma += __shfl_xor_sync(0xffffffffu, suma, 1);
    suma += __shfl_xor_sync(0xffffffffu, suma, 2);
    sumb += __shfl_xor_sync(0xffffffffu, sumb, 1);
    sumb += __shfl_xor_sync(0xffffffffu, sumb, 2);
    const float nla = g_nl[bh * S_ + rowa - i0 + i0];   // = g_nl[bh*S_+rowa]
    const float nlb = g_nl[bh * S_ + rowb];
    const float inva = 1.f / (fmaxf(fabsf(suma), nla) + EPS_);
    const float invb = 1.f / (fmaxf(fabsf(sumb), nlb) + EPS_);

    float sa = 0.f, sb = 0.f;
    #pragma unroll
    for (int n = 0; n < 16; ++n) {
        sa += hacc[n][0] + hacc[n][1];
        sb += hacc[n][2] + hacc[n][3];
    }
    sa *= inva; sb *= invb;
    sa += __shfl_xor_sync(0xffffffffu, sa, 1);
    sa += __shfl_xor_sync(0xffffffffu, sa, 2);
    sb += __shfl_xor_sync(0xffffffffu, sb, 1);
    sb += __shfl_xor_sync(0xffffffffu, sb, 2);
    const float mua = sa * (1.f / 128.f), mub = sb * (1.f / 128.f);

    float va = 0.f, vbv = 0.f;
    #pragma unroll
    for (int n = 0; n < 16; ++n) {
        float d0 = hacc[n][0] * inva - mua, d1 = hacc[n][1] * inva - mua;
        float d2 = hacc[n][2] * invb - mub, d3 = hacc[n][3] * invb - mub;
        va += d0 * d0 + d1 * d1;
        vbv += d2 * d2 + d3 * d3;
    }
    va += __shfl_xor_sync(0xffffffffu, va, 1);
    va += __shfl_xor_sync(0xffffffffu, va, 2);
    vbv += __shfl_xor_sync(0xffffffffu, vbv, 1);
    vbv += __shfl_xor_sync(0xffffffffu, vbv, 2);
    const float rsa = rsqrtf(va * (1.f / 128.f) + EPS_);
    const float rsb = rsqrtf(vbv * (1.f / 128.f) + EPS_);

    float* outa = out + ((size_t)(b * S_ + rowa)) * E_ + h * DH_;
    float* outb = out + ((size_t)(b * S_ + rowb)) * E_ + h * DH_;
    #pragma unroll
    for (int n = 0; n < 16; ++n) {
        const int d = n * 8 + 2 * tig;
        const float l0 = lnsc[h * DH_ + d], l1 = lnsc[h * DH_ + d + 1];
        float2 oa, ob;
        oa.x = (hacc[n][0] * inva - mua) * rsa * l0;
        oa.y = (hacc[n][1] * inva - mua) * rsa * l1;
        ob.x = (hacc[n][2] * invb - mub) * rsb * l0;
        ob.y = (hacc[n][3] * invb - mub) * rsb * l1;
        *(float2*)(outa + d) = oa;
        *(float2*)(outb + d) = ob;
    }
}

// =====================================================================
extern "C" void kernel_launch(void* const* d_in, const int* in_sizes, int n_in,
                              void* d_out, int out_size)
{
    const float* q  = (const float*)d_in[0];
    const float* k  = (const float*)d_in[1];
    const float* v  = (const float*)d_in[2];
    const float* Wi = (const float*)d_in[3];
    const float* bi = (const float*)d_in[4];
    const float* Wf = (const float*)d_in[5];
    const float* bf = (const float*)d_in[6];
    const float* ln = (const float*)d_in[7];
    float* out = (float*)d_out;

    cudaFuncSetAttribute(attn_k, cudaFuncAttributeMaxDynamicSharedMemorySize, SM_BYTES);

    gates_partial_k<<<dim3(32, NEC), 256>>>(q, k, v, Wi, Wf);
    scan_k<<<B_ * NH_, 1024>>>(bi, bf);
    attn_k<<<dim3(B_ * NH_, 8), 256, SM_BYTES>>>(q, k, v, ln, out);
}

// round 8
// speedup vs baseline: 2.4988x; 1.0134x over previous
#include <cuda_runtime.h>
#include <cuda_bf16.h>
#include <math.h>
#include <stdint.h>

#define B_   2
#define S_   1024
#define E_   2048
#define NH_  16
#define DH_  128
#define EPS_ 1e-6f
#define NEC  24
#define ECH  256          // 6144 / 24

#define FMA2(d, a, b)  asm("fma.rn.f32x2 %0, %1, %2, %0;" : "+l"(d) : "l"(a), "l"(b))
#define PACK2(d, x)    asm("mov.b64 %0, {%1, %1};" : "=l"(d) : "f"(x))

__device__ __forceinline__ void cpa16(uint32_t dst, const void* src) {
    asm volatile("cp.async.ca.shared.global [%0], [%1], 16;" :: "r"(dst), "l"(src));
}
__device__ __forceinline__ void cpa_commit() { asm volatile("cp.async.commit_group;"); }

// ---------------- warp-MMA helpers (sm_80-era PTX: safe under compute_103) ----------------
static __device__ __forceinline__ uint32_t pack_bf2(float x0, float x1) {
    uint32_t r; asm("cvt.rn.bf16x2.f32 %0, %1, %2;" : "=r"(r) : "f"(x1), "f"(x0)); return r;
}
static __device__ __forceinline__ float lo_f(uint32_t p) { return __uint_as_float(p << 16); }
static __device__ __forceinline__ float hi_f(uint32_t p) { return __uint_as_float(p & 0xffff0000u); }

#define LDSM4(r, a) \
    asm volatile("ldmatrix.sync.aligned.m8n8.x4.shared.b16 {%0,%1,%2,%3}, [%4];" \
        : "=r"((r)[0]), "=r"((r)[1]), "=r"((r)[2]), "=r"((r)[3]) : "r"(a))
#define LDSM4T(r, a) \
    asm volatile("ldmatrix.sync.aligned.m8n8.x4.trans.shared.b16 {%0,%1,%2,%3}, [%4];" \
        : "=r"((r)[0]), "=r"((r)[1]), "=r"((r)[2]), "=r"((r)[3]) : "r"(a))

static __device__ __forceinline__ void mma16816(float* c, const uint32_t* a, const uint32_t* b) {
    asm volatile("mma.sync.aligned.m16n8k16.row.col.f32.bf16.bf16.f32 "
        "{%0,%1,%2,%3}, {%4,%5,%6,%7}, {%8,%9}, {%0,%1,%2,%3};"
        : "+f"(c[0]), "+f"(c[1]), "+f"(c[2]), "+f"(c[3])
        : "r"(a[0]), "r"(a[1]), "r"(a[2]), "r"(a[3]), "r"(b[0]), "r"(b[1]));
}

__device__ float g_part[2 * NEC * B_ * NH_ * S_];
__device__ float g_a [B_ * NH_ * S_];
__device__ float g_rm[B_ * NH_ * S_];
__device__ float g_nl[B_ * NH_ * S_];

// ============== Kernel 1: gates, cp.async double-buffered ==============
__global__ __launch_bounds__(256) void gates_partial_k(
    const float* __restrict__ q, const float* __restrict__ k, const float* __restrict__ v,
    const float* __restrict__ Wi, const float* __restrict__ Wf)
{
    __shared__ float Xs[2][64 * 68];
    __shared__ float Ws[2][64 * 32];
    const int rt = blockIdx.x, ec = blockIdx.y;
    const int b = rt >> 4, s0 = (rt & 15) << 6, t = threadIdx.x;
    const int rgrp = t >> 3, hgrp = t & 7;

    auto pf = [&](int sub, int bufi) {
        const int e0 = ec * ECH + sub * 64;
        const float* xp = (e0 < E_) ? q : (e0 < 2 * E_) ? k : v;
        const int col0 = e0 & (E_ - 1);
        float* xd = Xs[bufi];
        float* wd = Ws[bufi];
        #pragma unroll
        for (int c = 0; c < 4; ++c) {
            int idx = t + c * 256, r = idx >> 4, q4 = (idx & 15) * 4;
            cpa16((uint32_t)__cvta_generic_to_shared(xd + r * 68 + q4),
                  xp + ((size_t)(b * S_ + s0 + r)) * E_ + col0 + q4);
        }
        #pragma unroll
        for (int c = 0; c < 2; ++c) {
            int idx = t + c * 256, ee = idx >> 3, cc = idx & 7, eg = e0 + ee;
            const float* src = (cc < 4) ? (Wi + eg * 16 + cc * 4)
                                        : (Wf + eg * 16 + (cc - 4) * 4);
            cpa16((uint32_t)__cvta_generic_to_shared(wd + ee * 32 + cc * 4), src);
        }
        cpa_commit();
    };

    unsigned long long acc2[2][2] = {};
    pf(0, 0);
    #pragma unroll 1
    for (int sub = 0; sub < 4; ++sub) {
        const int bufi = sub & 1;
        if (sub < 3) {
            pf(sub + 1, bufi ^ 1);
            asm volatile("cp.async.wait_group 1;");
        } else {
            asm volatile("cp.async.wait_group 0;");
        }
        __syncthreads();
        const float* xs = Xs[bufi];
        const float* ws = Ws[bufi];
        #pragma unroll 8
        for (int ee = 0; ee < 64; ++ee) {
            unsigned long long xp2[2];
            #pragma unroll
            for (int m = 0; m < 2; ++m) { float xv = xs[(rgrp * 2 + m) * 68 + ee]; PACK2(xp2[m], xv); }
            ulonglong2 wv = *(const ulonglong2*)(ws + ee * 32 + hgrp * 4);
            #pragma unroll
            for (int m = 0; m < 2; ++m) { FMA2(acc2[m][0], xp2[m], wv.x); FMA2(acc2[m][1], xp2[m], wv.y); }
        }
        __syncthreads();
    }
    #pragma unroll
    for (int m = 0; m < 2; ++m) {
        int s = s0 + rgrp * 2 + m;
        #pragma unroll
        for (int p = 0; p < 2; ++p) {
            float2 u = *(float2*)&acc2[m][p];
            #pragma unroll
            for (int hh = 0; hh < 2; ++hh) {
                int hcol = hgrp * 4 + p * 2 + hh;
                g_part[(((hcol >> 4) * NEC + ec) * (B_ * NH_) + b * NH_ + (hcol & 15)) * S_ + s] = hh ? u.y : u.x;
            }
        }
    }
}

// ============== Kernel 2: scans ==============
__global__ __launch_bounds__(1024, 1) void scan_k(const float* __restrict__ bi, const float* __restrict__ bf)
{
    __shared__ float buf[1024];
    const int bh = blockIdx.x, t = threadIdx.x, h = bh & 15;
    float ig = bi[h], fg = bf[h];
    #pragma unroll
    for (int ec = 0; ec < NEC; ++ec) {
        ig += g_part[((0 * NEC + ec) * (B_ * NH_) + bh) * S_ + t];
        fg += g_part[((1 * NEC + ec) * (B_ * NH_) + bh) * S_ + t];
    }
    float lf = fminf(fg, 0.f) - log1pf(expf(-fabsf(fg)));
    float x = lf;
    buf[t] = x; __syncthreads();
    for (int off = 1; off < 1024; off <<= 1) {
        float y = (t >= off) ? buf[t - off] : 0.f; __syncthreads();
        x += y; buf[t] = x; __syncthreads();
    }
    float cum = x, a = ig - cum;
    x = a; buf[t] = x; __syncthreads();
    for (int off = 1; off < 1024; off <<= 1) {
        float y = (t >= off) ? buf[t - off] : -3.4e38f; __syncthreads();
        x = fmaxf(x, y); buf[t] = x; __syncthreads();
    }
    g_a [bh * S_ + t] = a;
    g_rm[bh * S_ + t] = x;
    g_nl[bh * S_ + t] = expf(-(cum + x));
}

// ============== Kernel 3: HMMA bf16 attention + cp.async raw prefetch ==============
#define LDH  136
#define SM_KHI  0
#define SM_KLO  17408
#define SM_VHI  34816
#define SM_VLO  52224
#define SM_QHI  0          // Q staging aliases K region (freed after frag load)
#define SM_QLO  34816      // aliases V region
#define SM_RAWK 69632      // 64x128 f32
#define SM_RAWV 102400
#define SM_RAWA 135168     // 64 f32
#define SM_RMS  135424
#define SM_ERS  135936
#define SM_WCS  136448
#define SM_BYTES 136704

__global__ __launch_bounds__(256, 1) void attn_k(
    const float* __restrict__ q, const float* __restrict__ k,
    const float* __restrict__ v, const float* __restrict__ lnsc,
    float* __restrict__ out)
{
    extern __shared__ char smc[];
    const uint32_t smb = (uint32_t)__cvta_generic_to_shared(smc);
    float* rawk = (float*)(smc + SM_RAWK);
    float* rawv = (float*)(smc + SM_RAWV);
    float* rawa = (float*)(smc + SM_RAWA);
    float* rmS  = (float*)(smc + SM_RMS);
    float* erS  = (float*)(smc + SM_ERS);
    float* wcS  = (float*)(smc + SM_WCS);

    const int bh = blockIdx.x;
    const int b  = bh >> 4, h = bh & 15;
    const int ri = 7 - (int)blockIdx.y;
    const int i0 = ri << 7;
    const int t  = threadIdx.x;
    const int w  = t >> 5, lane = t & 31;
    const int gid = lane >> 2, tig = lane & 3;
    const float scale = 0.08838834764831845f;
    const int nj = 2 * ri + 2;

    auto pfetch = [&](int j0) {
        const float* kb = k + ((size_t)(b * S_ + j0)) * E_ + h * DH_;
        const float* vb = v + ((size_t)(b * S_ + j0)) * E_ + h * DH_;
        #pragma unroll
        for (int it = 0; it < 8; ++it) {
            int idx = t + it * 256, r = idx >> 5, d4 = (idx & 31) * 4;
            cpa16(smb + SM_RAWK + (uint32_t)(r * 128 + d4) * 4, kb + (size_t)r * E_ + d4);
            cpa16(smb + SM_RAWV + (uint32_t)(r * 128 + d4) * 4, vb + (size_t)r * E_ + d4);
        }
        if (t < 16) cpa16(smb + SM_RAWA + t * 16, g_a + bh * S_ + j0 + t * 4);
        cpa_commit();
    };
    pfetch(0);   // overlaps Q staging below

    // ---- Q staging: fold scale, split hi/lo into (reused) K/V regions ----
    {
        const float* qb = q + ((size_t)(b * S_ + i0)) * E_ + h * DH_;
        #pragma unroll
        for (int it = 0; it < 16; ++it) {
            int idx = t + it * 256;
            int r = idx >> 5, d4 = (idx & 31) * 4;
            float4 x = *(const float4*)(qb + (size_t)r * E_ + d4);
            x.x *= scale; x.y *= scale; x.z *= scale; x.w *= scale;
            uint32_t h01 = pack_bf2(x.x, x.y), h23 = pack_bf2(x.z, x.w);
            uint32_t l01 = pack_bf2(x.x - lo_f(h01), x.y - hi_f(h01));
            uint32_t l23 = pack_bf2(x.z - lo_f(h23), x.w - hi_f(h23));
            uint32_t bo = (uint32_t)(r * LDH + d4) * 2;
            *(uint2*)(smc + SM_QHI + bo) = make_uint2(h01, h23);
            *(uint2*)(smc + SM_QLO + bo) = make_uint2(l01, l23);
        }
        if (t < 128) rmS[t] = g_rm[bh * S_ + i0 + t];
    }
    __syncthreads();

    // ---- Q fragments into registers ----
    uint32_t qh[8][4], ql[8][4];
    {
        uint32_t rowq = (uint32_t)(w * 16 + (lane & 7) + 8 * ((lane >> 3) & 1));
        #pragma unroll
        for (int kk = 0; kk < 8; ++kk) {
            uint32_t off = (rowq * LDH + kk * 16 + 8 * (lane >> 4)) * 2;
            LDSM4(qh[kk], smb + SM_QHI + off);
            LDSM4(ql[kk], smb + SM_QLO + off);
        }
    }

    float hacc[16][4];
    #pragma unroll
    for (int n = 0; n < 16; ++n)
        #pragma unroll
        for (int e = 0; e < 4; ++e) hacc[n][e] = 0.f;
    float suma = 0.f, sumb = 0.f;
    const int rowa = i0 + w * 16 + gid;
    const int rowb = rowa + 8;

    #pragma unroll 1
    for (int jt = 0; jt < nj; ++jt) {
        const int j0 = jt << 6;
        asm volatile("cp.async.wait_group 0;");
        __syncthreads();   // raw ready; all warps done with Q frags / prev tile's K,V

        // ---- convert raw f32 -> bf16 hi/lo K,V ----
        #pragma unroll
        for (int it = 0; it < 8; ++it) {
            int idx = t + it * 256, r = idx >> 5, d4 = (idx & 31) * 4;
            uint32_t bo = (uint32_t)(r * LDH + d4) * 2;
            float4 x = *(const float4*)(rawk + r * 128 + d4);
            uint32_t h01 = pack_bf2(x.x, x.y), h23 = pack_bf2(x.z, x.w);
            uint32_t l01 = pack_bf2(x.x - lo_f(h01), x.y - hi_f(h01));
            uint32_t l23 = pack_bf2(x.z - lo_f(h23), x.w - hi_f(h23));
            *(uint2*)(smc + SM_KHI + bo) = make_uint2(h01, h23);
            *(uint2*)(smc + SM_KLO + bo) = make_uint2(l01, l23);
            float4 y = *(const float4*)(rawv + r * 128 + d4);
            uint32_t g01 = pack_bf2(y.x, y.y), g23 = pack_bf2(y.z, y.w);
            uint32_t m01 = pack_bf2(y.x - lo_f(g01), y.y - hi_f(g01));
            uint32_t m23 = pack_bf2(y.z - lo_f(g23), y.w - hi_f(g23));
            *(uint2*)(smc + SM_VHI + bo) = make_uint2(g01, g23);
            *(uint2*)(smc + SM_VLO + bo) = make_uint2(m01, m23);
        }
        // ---- exp tables from raw a ----
        if (t < 128) {
            float m0 = -3.4e38f;
            #pragma unroll 8
            for (int c = 0; c < 64; ++c) m0 = fmaxf(m0, rawa[c]);
            if (t < 64) wcS[t] = __expf(rawa[t] - m0);
            erS[t] = __expf(fminf(m0 - rmS[t], 80.f));
        }
        __syncthreads();   // conversion + tables done; raw free for next prefetch
        if (jt + 1 < nj) pfetch(j0 + 64);

        // ---- QK: S = Q K^T (3 compensated MMAs) ----
        float sacc[8][4];
        #pragma unroll
        for (int n = 0; n < 8; ++n)
            #pragma unroll
            for (int e = 0; e < 4; ++e) sacc[n][e] = 0.f;
        {
            uint32_t rowk = (uint32_t)((lane & 7) + 8 * (lane >> 4));
            uint32_t colk = (uint32_t)(8 * ((lane >> 3) & 1));
            #pragma unroll
            for (int kk = 0; kk < 8; ++kk) {
                #pragma unroll
                for (int np = 0; np < 4; ++np) {
                    uint32_t off = ((np * 16 + rowk) * LDH + kk * 16 + colk) * 2;
                    uint32_t bhf[4], blf[4];
                    LDSM4(bhf, smb + SM_KHI + off);
                    LDSM4(blf, smb + SM_KLO + off);
                    mma16816(sacc[2 * np],     qh[kk], bhf);
                    mma16816(sacc[2 * np],     qh[kk], blf);
                    mma16816(sacc[2 * np],     ql[kk], bhf);
                    mma16816(sacc[2 * np + 1], qh[kk], bhf + 2);
                    mma16816(sacc[2 * np + 1], qh[kk], blf + 2);
                    mma16816(sacc[2 * np + 1], ql[kk], bhf + 2);
                }
            }
        }

        // ---- mask + exp weights ----
        const float era = erS[w * 16 + gid];
        const float erb = erS[w * 16 + gid + 8];
        #pragma unroll
        for (int n = 0; n < 8; ++n) {
            const int cbase = n * 8 + 2 * tig;
            const int c0 = j0 + cbase, c1 = c0 + 1;
            const float w0 = wcS[cbase], w1 = wcS[cbase + 1];
            float p0 = (c0 <= rowa) ? sacc[n][0] * w0 * era : 0.f;
            float p1 = (c1 <= rowa) ? sacc[n][1] * w1 * era : 0.f;
            float p2 = (c0 <= rowb) ? sacc[n][2] * w0 * erb : 0.f;
            float p3 = (c1 <= rowb) ? sacc[n][3] * w1 * erb : 0.f;
            suma += p0 + p1; sumb += p2 + p3;
            sacc[n][0] = p0; sacc[n][1] = p1; sacc[n][2] = p2; sacc[n][3] = p3;
        }

        // ---- AV: H += P V (3 compensated MMAs) ----
        {
            uint32_t rowv = (uint32_t)((lane & 7) + 8 * ((lane >> 3) & 1));
            uint32_t colv = (uint32_t)(8 * (lane >> 4));
            #pragma unroll
            for (int kk = 0; kk < 4; ++kk) {
                uint32_t pah[4], pal[4];
                pah[0] = pack_bf2(sacc[2*kk][0],   sacc[2*kk][1]);
                pah[1] = pack_bf2(sacc[2*kk][2],   sacc[2*kk][3]);
                pah[2] = pack_bf2(sacc[2*kk+1][0], sacc[2*kk+1][1]);
                pah[3] = pack_bf2(sacc[2*kk+1][2], sacc[2*kk+1][3]);
                pal[0] = pack_bf2(sacc[2*kk][0]   - lo_f(pah[0]), sacc[2*kk][1]   - hi_f(pah[0]));
                pal[1] = pack_bf2(sacc[2*kk][2]   - lo_f(pah[1]), sacc[2*kk][3]   - hi_f(pah[1]));
                pal[2] = pack_bf2(sacc[2*kk+1][0] - lo_f(pah[2]), sacc[2*kk+1][1] - hi_f(pah[2]));
                pal[3] = pack_bf2(sacc[2*kk+1][2] - lo_f(pah[3]), sacc[2*kk+1][3] - hi_f(pah[3]));
                #pragma unroll
                for (int np = 0; np < 8; ++np) {
                    uint32_t off = ((kk * 16 + rowv) * LDH + np * 16 + colv) * 2;
                    uint32_t bvh[4], bvl[4];
                    LDSM4T(bvh, smb + SM_VHI + off);
                    LDSM4T(bvl, smb + SM_VLO + off);
                    mma16816(hacc[2 * np],     pah, bvh);
                    mma16816(hacc[2 * np],     pah, bvl);
                    mma16816(hacc[2 * np],     pal, bvh);
                    mma16816(hacc[2 * np + 1], pah, bvh + 2);
                    mma16816(hacc[2 * np + 1], pah, bvl + 2);
                    mma16816(hacc[2 * np + 1], pal, bvh + 2);
                }
            }
        }
    }

    // ---- epilogue ----
    suma += __shfl_xor_sync(0xffffffffu, suma, 1);
    suma += __shfl_xor_sync(0xffffffffu, suma, 2);
    sumb += __shfl_xor_sync(0xffffffffu, sumb, 1);
    sumb += __shfl_xor_sync(0xffffffffu, sumb, 2);
    const float nla = g_nl[bh * S_ + rowa];
    const float nlb = g_nl[bh * S_ + rowb];
    const float inva = 1.f / (fmaxf(fabsf(suma), nla) + EPS_);
    const float invb = 1.f / (fmaxf(fabsf(sumb), nlb) + EPS_);

    float sa = 0.f, sb = 0.f;
    #pragma unroll
    for (int n = 0; n < 16; ++n) {
        sa += hacc[n][0] + hacc[n][1];
        sb += hacc[n][2] + hacc[n][3];
    }
    sa *= inva; sb *= invb;
    sa += __shfl_xor_sync(0xffffffffu, sa, 1);
    sa += __shfl_xor_sync(0xffffffffu, sa, 2);
    sb += __shfl_xor_sync(0xffffffffu, sb, 1);
    sb += __shfl_xor_sync(0xffffffffu, sb, 2);
    const float mua = sa * (1.f / 128.f), mub = sb * (1.f / 128.f);

    float va = 0.f, vbv = 0.f;
    #pragma unroll
    for (int n = 0; n < 16; ++n) {
        float d0 = hacc[n][0] * inva - mua, d1 = hacc[n][1] * inva - mua;
        float d2 = hacc[n][2] * invb - mub, d3 = hacc[n][3] * invb - mub;
        va += d0 * d0 + d1 * d1;
        vbv += d2 * d2 + d3 * d3;
    }
    va += __shfl_xor_sync(0xffffffffu, va, 1);
    va += __shfl_xor_sync(0xffffffffu, va, 2);
    vbv += __shfl_xor_sync(0xffffffffu, vbv, 1);
    vbv += __shfl_xor_sync(0xffffffffu, vbv, 2);
    const float rsa = rsqrtf(va * (1.f / 128.f) + EPS_);
    const float rsb = rsqrtf(vbv * (1.f / 128.f) + EPS_);

    float* outa = out + ((size_t)(b * S_ + rowa)) * E_ + h * DH_;
    float* outb = out + ((size_t)(b * S_ + rowb)) * E_ + h * DH_;
    #pragma unroll
    for (int n = 0; n < 16; ++n) {
        const int d = n * 8 + 2 * tig;
        const float l0 = lnsc[h * DH_ + d], l1 = lnsc[h * DH_ + d + 1];
        float2 oa, ob;
        oa.x = (hacc[n][0] * inva - mua) * rsa * l0;
        oa.y = (hacc[n][1] * inva - mua) * rsa * l1;
        ob.x = (hacc[n][2] * invb - mub) * rsb * l0;
        ob.y = (hacc[n][3] * invb - mub) * rsb * l1;
        *(float2*)(outa + d) = oa;
        *(float2*)(outb + d) = ob;
    }
}

// =====================================================================
extern "C" void kernel_launch(void* const* d_in, const int* in_sizes, int n_in,
                              void* d_out, int out_size)
{
    const float* q  = (const float*)d_in[0];
    const float* k  = (const float*)d_in[1];
    const float* v  = (const float*)d_in[2];
    const float* Wi = (const float*)d_in[3];
    const float* bi = (const float*)d_in[4];
    const float* Wf = (const float*)d_in[5];
    const float* bf = (const float*)d_in[6];
    const float* ln = (const float*)d_in[7];
    float* out = (float*)d_out;

    cudaFuncSetAttribute(attn_k, cudaFuncAttributeMaxDynamicSharedMemorySize, SM_BYTES);

    gates_partial_k<<<dim3(32, NEC), 256>>>(q, k, v, Wi, Wf);
    scan_k<<<B_ * NH_, 1024>>>(bi, bf);
    attn_k<<<dim3(B_ * NH_, 8), 256, SM_BYTES>>>(q, k, v, ln, out);
}

// round 9
// speedup vs baseline: 2.5663x; 1.0270x over previous
#include <cuda_runtime.h>
#include <cuda_bf16.h>
#include <math.h>
#include <stdint.h>

#define B_   2
#define S_   1024
#define E_   2048
#define NH_  16
#define DH_  128
#define EPS_ 1e-6f
#define NEC  24
#define ECH  256          // 6144 / 24

#define FMA2(d, a, b)  asm("fma.rn.f32x2 %0, %1, %2, %0;" : "+l"(d) : "l"(a), "l"(b))
#define PACK2(d, x)    asm("mov.b64 %0, {%1, %1};" : "=l"(d) : "f"(x))

__device__ __forceinline__ void cpa16(uint32_t dst, const void* src) {
    asm volatile("cp.async.ca.shared.global [%0], [%1], 16;" :: "r"(dst), "l"(src));
}
__device__ __forceinline__ void cpa_commit() { asm volatile("cp.async.commit_group;"); }

// ---------------- warp-MMA helpers (sm_80-era PTX: safe under compute_103) ----------------
static __device__ __forceinline__ uint32_t pack_bf2(float x0, float x1) {
    uint32_t r; asm("cvt.rn.bf16x2.f32 %0, %1, %2;" : "=r"(r) : "f"(x1), "f"(x0)); return r;
}
static __device__ __forceinline__ float lo_f(uint32_t p) { return __uint_as_float(p << 16); }
static __device__ __forceinline__ float hi_f(uint32_t p) { return __uint_as_float(p & 0xffff0000u); }

#define LDSM4(r, a) \
    asm volatile("ldmatrix.sync.aligned.m8n8.x4.shared.b16 {%0,%1,%2,%3}, [%4];" \
        : "=r"((r)[0]), "=r"((r)[1]), "=r"((r)[2]), "=r"((r)[3]) : "r"(a))
#define LDSM4T(r, a) \
    asm volatile("ldmatrix.sync.aligned.m8n8.x4.trans.shared.b16 {%0,%1,%2,%3}, [%4];" \
        : "=r"((r)[0]), "=r"((r)[1]), "=r"((r)[2]), "=r"((r)[3]) : "r"(a))

static __device__ __forceinline__ void mma16816(float* c, const uint32_t* a, const uint32_t* b) {
    asm volatile("mma.sync.aligned.m16n8k16.row.col.f32.bf16.bf16.f32 "
        "{%0,%1,%2,%3}, {%4,%5,%6,%7}, {%8,%9}, {%0,%1,%2,%3};"
        : "+f"(c[0]), "+f"(c[1]), "+f"(c[2]), "+f"(c[3])
        : "r"(a[0]), "r"(a[1]), "r"(a[2]), "r"(a[3]), "r"(b[0]), "r"(b[1]));
}

__device__ float g_part[2 * NEC * B_ * NH_ * S_];
__device__ float g_a [B_ * NH_ * S_];
__device__ float g_rm[B_ * NH_ * S_];
__device__ float g_nl[B_ * NH_ * S_];

// ============== Kernel 1: gates, 4-deep cp.async pipeline (dynamic smem) ==============
#define GX (64 * 68)
#define GW (64 * 32)
#define GSM_BYTES (4 * (GX + GW) * 4)   // 102400

__global__ __launch_bounds__(256) void gates_partial_k(
    const float* __restrict__ q, const float* __restrict__ k, const float* __restrict__ v,
    const float* __restrict__ Wi, const float* __restrict__ Wf)
{
    extern __shared__ float gsm[];
    const int rt = blockIdx.x, ec = blockIdx.y;
    const int b = rt >> 4, s0 = (rt & 15) << 6, t = threadIdx.x;
    const int rgrp = t >> 3, hgrp = t & 7;

    auto pf = [&](int sub) {
        const int e0 = ec * ECH + sub * 64;
        const float* xp = (e0 < E_) ? q : (e0 < 2 * E_) ? k : v;
        const int col0 = e0 & (E_ - 1);
        float* xd = gsm + sub * (GX + GW);
        float* wd = xd + GX;
        #pragma unroll
        for (int c = 0; c < 4; ++c) {
            int idx = t + c * 256, r = idx >> 4, q4 = (idx & 15) * 4;
            cpa16((uint32_t)__cvta_generic_to_shared(xd + r * 68 + q4),
                  xp + ((size_t)(b * S_ + s0 + r)) * E_ + col0 + q4);
        }
        #pragma unroll
        for (int c = 0; c < 2; ++c) {
            int idx = t + c * 256, ee = idx >> 3, cc = idx & 7, eg = e0 + ee;
            const float* src = (cc < 4) ? (Wi + eg * 16 + cc * 4)
                                        : (Wf + eg * 16 + (cc - 4) * 4);
            cpa16((uint32_t)__cvta_generic_to_shared(wd + ee * 32 + cc * 4), src);
        }
        cpa_commit();
    };

    pf(0); pf(1); pf(2); pf(3);

    unsigned long long acc2[2][2] = {};
    #define GSTEP(sub, wn) do { \
        asm volatile("cp.async.wait_group %0;" :: "n"(wn)); \
        __syncthreads(); \
        const float* xs = gsm + (sub) * (GX + GW); \
        const float* ws = xs + GX; \
        _Pragma("unroll 8") \
        for (int ee = 0; ee < 64; ++ee) { \
            unsigned long long xp2[2]; \
            _Pragma("unroll") \
            for (int m = 0; m < 2; ++m) { float xv = xs[(rgrp * 2 + m) * 68 + ee]; PACK2(xp2[m], xv); } \
            ulonglong2 wv = *(const ulonglong2*)(ws + ee * 32 + hgrp * 4); \
            _Pragma("unroll") \
            for (int m = 0; m < 2; ++m) { FMA2(acc2[m][0], xp2[m], wv.x); FMA2(acc2[m][1], xp2[m], wv.y); } \
        } \
    } while (0)

    GSTEP(0, 3);
    GSTEP(1, 2);
    GSTEP(2, 1);
    GSTEP(3, 0);
    #undef GSTEP

    #pragma unroll
    for (int m = 0; m < 2; ++m) {
        int s = s0 + rgrp * 2 + m;
        #pragma unroll
        for (int p = 0; p < 2; ++p) {
            float2 u = *(float2*)&acc2[m][p];
            #pragma unroll
            for (int hh = 0; hh < 2; ++hh) {
                int hcol = hgrp * 4 + p * 2 + hh;
                g_part[(((hcol >> 4) * NEC + ec) * (B_ * NH_) + b * NH_ + (hcol & 15)) * S_ + s] = hh ? u.y : u.x;
            }
        }
    }
}

// ============== Kernel 2: scans ==============
__global__ __launch_bounds__(1024, 1) void scan_k(const float* __restrict__ bi, const float* __restrict__ bf)
{
    __shared__ float buf[1024];
    const int bh = blockIdx.x, t = threadIdx.x, h = bh & 15;
    float ig = bi[h], fg = bf[h];
    #pragma unroll
    for (int ec = 0; ec < NEC; ++ec) {
        ig += g_part[((0 * NEC + ec) * (B_ * NH_) + bh) * S_ + t];
        fg += g_part[((1 * NEC + ec) * (B_ * NH_) + bh) * S_ + t];
    }
    float lf = fminf(fg, 0.f) - log1pf(expf(-fabsf(fg)));
    float x = lf;
    buf[t] = x; __syncthreads();
    for (int off = 1; off < 1024; off <<= 1) {
        float y = (t >= off) ? buf[t - off] : 0.f; __syncthreads();
        x += y; buf[t] = x; __syncthreads();
    }
    float cum = x, a = ig - cum;
    x = a; buf[t] = x; __syncthreads();
    for (int off = 1; off < 1024; off <<= 1) {
        float y = (t >= off) ? buf[t - off] : -3.4e38f; __syncthreads();
        x = fmaxf(x, y); buf[t] = x; __syncthreads();
    }
    g_a [bh * S_ + t] = a;
    g_rm[bh * S_ + t] = x;
    g_nl[bh * S_ + t] = expf(-(cum + x));
}

// ============== Kernel 3: HMMA bf16 attention (R7 version — fastest measured) ==============
#define LDH  136
#define SM_QHI 0
#define SM_QLO 34816
#define SM_KHI 69632
#define SM_KLO 87040
#define SM_VHI 104448
#define SM_VLO 121856
#define SM_AS  139264
#define SM_RMS 139520
#define SM_ERS 140032
#define SM_WCS 140544
#define SM_BYTES 140800

__global__ __launch_bounds__(256, 1) void attn_k(
    const float* __restrict__ q, const float* __restrict__ k,
    const float* __restrict__ v, const float* __restrict__ lnsc,
    float* __restrict__ out)
{
    extern __shared__ char smc[];
    const uint32_t smb = (uint32_t)__cvta_generic_to_shared(smc);
    float* aS  = (float*)(smc + SM_AS);
    float* rmS = (float*)(smc + SM_RMS);
    float* erS = (float*)(smc + SM_ERS);
    float* wcS = (float*)(smc + SM_WCS);

    const int bh = blockIdx.x;
    const int b  = bh >> 4, h = bh & 15;
    const int ri = 7 - (int)blockIdx.y;      // heavy CTAs first
    const int i0 = ri << 7;
    const int t  = threadIdx.x;
    const int w  = t >> 5, lane = t & 31;
    const int gid = lane >> 2, tig = lane & 3;
    const float scale = 0.08838834764831845f;

    // ---- Q load: fold scale, bf16 hi/lo split into padded row-major smem ----
    {
        const float* qb = q + ((size_t)(b * S_ + i0)) * E_ + h * DH_;
        #pragma unroll
        for (int it = 0; it < 16; ++it) {
            int idx = t + it * 256;
            int r = idx >> 5, d4 = (idx & 31) * 4;
            float4 x = *(const float4*)(qb + (size_t)r * E_ + d4);
            x.x *= scale; x.y *= scale; x.z *= scale; x.w *= scale;
            uint32_t h01 = pack_bf2(x.x, x.y), h23 = pack_bf2(x.z, x.w);
            uint32_t l01 = pack_bf2(x.x - lo_f(h01), x.y - hi_f(h01));
            uint32_t l23 = pack_bf2(x.z - lo_f(h23), x.w - hi_f(h23));
            uint32_t bo = (uint32_t)(r * LDH + d4) * 2;
            *(uint2*)(smc + SM_QHI + bo) = make_uint2(h01, h23);
            *(uint2*)(smc + SM_QLO + bo) = make_uint2(l01, l23);
        }
        if (t < 128) rmS[t] = g_rm[bh * S_ + i0 + t];
    }
    __syncthreads();

    // ---- cache Q fragments in registers (A-operand layout) ----
    uint32_t qh[8][4], ql[8][4];
    {
        uint32_t rowq = (uint32_t)(w * 16 + (lane & 7) + 8 * ((lane >> 3) & 1));
        #pragma unroll
        for (int kk = 0; kk < 8; ++kk) {
            uint32_t off = (rowq * LDH + kk * 16 + 8 * (lane >> 4)) * 2;
            LDSM4(qh[kk], smb + SM_QHI + off);
            LDSM4(ql[kk], smb + SM_QLO + off);
        }
    }

    float hacc[16][4];
    #pragma unroll
    for (int n = 0; n < 16; ++n)
        #pragma unroll
        for (int e = 0; e < 4; ++e) hacc[n][e] = 0.f;
    float suma = 0.f, sumb = 0.f;

    const int rowa = i0 + w * 16 + gid;
    const int rowb = rowa + 8;
    const int nj = 2 * ri + 2;

    for (int jt = 0; jt < nj; ++jt) {
        const int j0 = jt << 6;
        __syncthreads();
        // ---- K,V tiles: split hi/lo ----
        {
            const float* kb = k + ((size_t)(b * S_ + j0)) * E_ + h * DH_;
            const float* vb = v + ((size_t)(b * S_ + j0)) * E_ + h * DH_;
            #pragma unroll
            for (int it = 0; it < 8; ++it) {
                int idx = t + it * 256;
                int r = idx >> 5, d4 = (idx & 31) * 4;
                uint32_t bo = (uint32_t)(r * LDH + d4) * 2;
                float4 x = *(const float4*)(kb + (size_t)r * E_ + d4);
                uint32_t h01 = pack_bf2(x.x, x.y), h23 = pack_bf2(x.z, x.w);
                uint32_t l01 = pack_bf2(x.x - lo_f(h01), x.y - hi_f(h01));
                uint32_t l23 = pack_bf2(x.z - lo_f(h23), x.w - hi_f(h23));
                *(uint2*)(smc + SM_KHI + bo) = make_uint2(h01, h23);
                *(uint2*)(smc + SM_KLO + bo) = make_uint2(l01, l23);
                float4 y = *(const float4*)(vb + (size_t)r * E_ + d4);
                uint32_t g01 = pack_bf2(y.x, y.y), g23 = pack_bf2(y.z, y.w);
                uint32_t m01 = pack_bf2(y.x - lo_f(g01), y.y - hi_f(g01));
                uint32_t m23 = pack_bf2(y.z - lo_f(g23), y.w - hi_f(g23));
                *(uint2*)(smc + SM_VHI + bo) = make_uint2(g01, g23);
                *(uint2*)(smc + SM_VLO + bo) = make_uint2(m01, m23);
            }
            if (t < 64) aS[t] = g_a[bh * S_ + j0 + t];
        }
        __syncthreads();
        // ---- exp tables ----
        if (t < 128) {
            float m0 = -3.4e38f;
            #pragma unroll 8
            for (int c = 0; c < 64; ++c) m0 = fmaxf(m0, aS[c]);
            if (t < 64) wcS[t] = __expf(aS[t] - m0);
            erS[t] = __expf(fminf(m0 - rmS[t], 80.f));
        }
        __syncthreads();

        // ---- QK: S = Q K^T (3 compensated MMAs) ----
        float sacc[8][4];
        #pragma unroll
        for (int n = 0; n < 8; ++n)
            #pragma unroll
            for (int e = 0; e < 4; ++e) sacc[n][e] = 0.f;
        {
            uint32_t rowk = (uint32_t)((lane & 7) + 8 * (lane >> 4));
            uint32_t colk = (uint32_t)(8 * ((lane >> 3) & 1));
            #pragma unroll
            for (int kk = 0; kk < 8; ++kk) {
                #pragma unroll
                for (int np = 0; np < 4; ++np) {
                    uint32_t off = ((np * 16 + rowk) * LDH + kk * 16 + colk) * 2;
                    uint32_t bhf[4], blf[4];
                    LDSM4(bhf, smb + SM_KHI + off);
                    LDSM4(blf, smb + SM_KLO + off);
                    mma16816(sacc[2 * np],     qh[kk], bhf);
                    mma16816(sacc[2 * np],     qh[kk], blf);
                    mma16816(sacc[2 * np],     ql[kk], bhf);
                    mma16816(sacc[2 * np + 1], qh[kk], bhf + 2);
                    mma16816(sacc[2 * np + 1], qh[kk], blf + 2);
                    mma16816(sacc[2 * np + 1], ql[kk], bhf + 2);
                }
            }
        }

        // ---- S -> P, causal mask, rowsums ----
        const float era = erS[w * 16 + gid];
        const float erb = erS[w * 16 + gid + 8];
        #pragma unroll
        for (int n = 0; n < 8; ++n) {
            const int cbase = n * 8 + 2 * tig;
            const int c0 = j0 + cbase, c1 = c0 + 1;
            const float w0 = wcS[cbase], w1 = wcS[cbase + 1];
            float p0 = (c0 <= rowa) ? sacc[n][0] * w0 * era : 0.f;
            float p1 = (c1 <= rowa) ? sacc[n][1] * w1 * era : 0.f;
            float p2 = (c0 <= rowb) ? sacc[n][2] * w0 * erb : 0.f;
            float p3 = (c1 <= rowb) ? sacc[n][3] * w1 * erb : 0.f;
            suma += p0 + p1; sumb += p2 + p3;
            sacc[n][0] = p0; sacc[n][1] = p1; sacc[n][2] = p2; sacc[n][3] = p3;
        }

        // ---- AV: H += P V (3 compensated MMAs) ----
        {
            uint32_t rowv = (uint32_t)((lane & 7) + 8 * ((lane >> 3) & 1));
            uint32_t colv = (uint32_t)(8 * (lane >> 4));
            #pragma unroll
            for (int kk = 0; kk < 4; ++kk) {
                uint32_t pah[4], pal[4];
                pah[0] = pack_bf2(sacc[2*kk][0],   sacc[2*kk][1]);
                pah[1] = pack_bf2(sacc[2*kk][2],   sacc[2*kk][3]);
                pah[2] = pack_bf2(sacc[2*kk+1][0], sacc[2*kk+1][1]);
                pah[3] = pack_bf2(sacc[2*kk+1][2], sacc[2*kk+1][3]);
                pal[0] = pack_bf2(sacc[2*kk][0]   - lo_f(pah[0]), sacc[2*kk][1]   - hi_f(pah[0]));
                pal[1] = pack_bf2(sacc[2*kk][2]   - lo_f(pah[1]), sacc[2*kk][3]   - hi_f(pah[1]));
                pal[2] = pack_bf2(sacc[2*kk+1][0] - lo_f(pah[2]), sacc[2*kk+1][1] - hi_f(pah[2]));
                pal[3] = pack_bf2(sacc[2*kk+1][2] - lo_f(pah[3]), sacc[2*kk+1][3] - hi_f(pah[3]));
                #pragma unroll
                for (int np = 0; np < 8; ++np) {
                    uint32_t off = ((kk * 16 + rowv) * LDH + np * 16 + colv) * 2;
                    uint32_t bvh[4], bvl[4];
                    LDSM4T(bvh, smb + SM_VHI + off);
                    LDSM4T(bvl, smb + SM_VLO + off);
                    mma16816(hacc[2 * np],     pah, bvh);
                    mma16816(hacc[2 * np],     pah, bvl);
                    mma16816(hacc[2 * np],     pal, bvh);
                    mma16816(hacc[2 * np + 1], pah, bvh + 2);
                    mma16816(hacc[2 * np + 1], pah, bvl + 2);
                    mma16816(hacc[2 * np + 1], pal, bvh + 2);
                }
            }
        }
    }

    // ---- epilogue ----
    suma += __shfl_xor_sync(0xffffffffu, suma, 1);
    suma += __shfl_xor_sync(0xffffffffu, suma, 2);
    sumb += __shfl_xor_sync(0xffffffffu, sumb, 1);
    sumb += __shfl_xor_sync(0xffffffffu, sumb, 2);
    const float nla = g_nl[bh * S_ + rowa];
    const float nlb = g_nl[bh * S_ + rowb];
    const float inva = 1.f / (fmaxf(fabsf(suma), nla) + EPS_);
    const float invb = 1.f / (fmaxf(fabsf(sumb), nlb) + EPS_);

    float sa = 0.f, sb = 0.f;
    #pragma unroll
    for (int n = 0; n < 16; ++n) {
        sa += hacc[n][0] + hacc[n][1];
        sb += hacc[n][2] + hacc[n][3];
    }
    sa *= inva; sb *= invb;
    sa += __shfl_xor_sync(0xffffffffu, sa, 1);
    sa += __shfl_xor_sync(0xffffffffu, sa, 2);
    sb += __shfl_xor_sync(0xffffffffu, sb, 1);
    sb += __shfl_xor_sync(0xffffffffu, sb, 2);
    const float mua = sa * (1.f / 128.f), mub = sb * (1.f / 128.f);

    float va = 0.f, vbv = 0.f;
    #pragma unroll
    for (int n = 0; n < 16; ++n) {
        float d0 = hacc[n][0] * inva - mua, d1 = hacc[n][1] * inva - mua;
        float d2 = hacc[n][2] * invb - mub, d3 = hacc[n][3] * invb - mub;
        va += d0 * d0 + d1 * d1;
        vbv += d2 * d2 + d3 * d3;
    }
    va += __shfl_xor_sync(0xffffffffu, va, 1);
    va += __shfl_xor_sync(0xffffffffu, va, 2);
    vbv += __shfl_xor_sync(0xffffffffu, vbv, 1);
    vbv += __shfl_xor_sync(0xffffffffu, vbv, 2);
    const float rsa = rsqrtf(va * (1.f / 128.f) + EPS_);
    const float rsb = rsqrtf(vbv * (1.f / 128.f) + EPS_);

    float* outa = out + ((size_t)(b * S_ + rowa)) * E_ + h * DH_;
    float* outb = out + ((size_t)(b * S_ + rowb)) * E_ + h * DH_;
    #pragma unroll
    for (int n = 0; n < 16; ++n) {
        const int d = n * 8 + 2 * tig;
        const float l0 = lnsc[h * DH_ + d], l1 = lnsc[h * DH_ + d + 1];
        float2 oa, ob;
        oa.x = (hacc[n][0] * inva - mua) * rsa * l0;
        oa.y = (hacc[n][1] * inva - mua) * rsa * l1;
        ob.x = (hacc[n][2] * invb - mub) * rsb * l0;
        ob.y = (hacc[n][3] * invb - mub) * rsb * l1;
        *(float2*)(outa + d) = oa;
        *(float2*)(outb + d) = ob;
    }
}

// =====================================================================
extern "C" void kernel_launch(void* const* d_in, const int* in_sizes, int n_in,
                              void* d_out, int out_size)
{
    const float* q  = (const float*)d_in[0];
    const float* k  = (const float*)d_in[1];
    const float* v  = (const float*)d_in[2];
    const float* Wi = (const float*)d_in[3];
    const float* bi = (const float*)d_in[4];
    const float* Wf = (const float*)d_in[5];
    const float* bf = (const float*)d_in[6];
    const float* ln = (const float*)d_in[7];
    float* out = (float*)d_out;

    cudaFuncSetAttribute(gates_partial_k, cudaFuncAttributeMaxDynamicSharedMemorySize, GSM_BYTES);
    cudaFuncSetAttribute(attn_k, cudaFuncAttributeMaxDynamicSharedMemorySize, SM_BYTES);

    gates_partial_k<<<dim3(32, NEC), 256, GSM_BYTES>>>(q, k, v, Wi, Wf);
    scan_k<<<B_ * NH_, 1024>>>(bi, bf);
    attn_k<<<dim3(B_ * NH_, 8), 256, SM_BYTES>>>(q, k, v, ln, out);
}